// round 17
// speedup vs baseline: 17.2113x; 1.1025x over previous
#include <cuda_runtime.h>
#include <cuda_bf16.h>
#include <cuda_fp16.h>
#include <math.h>
#include <stdint.h>

// Problem constants
#define B_ 2
#define T_ 2048
#define M_ 1024
#define C_ 512
#define H_ 8
#define D_ 64
#define BH_ (B_*H_)

// ---------------------------------------------------------------------------
// Scratch (device globals)
// ---------------------------------------------------------------------------
__device__ float g_qkvx[(size_t)B_ * T_ * 3 * C_];
__device__ float g_qkvy[(size_t)B_ * M_ * 3 * C_];
__device__ float g_Gp [(size_t)BH_ * 16 * D_ * D_];
__device__ float g_G  [(size_t)BH_ * D_ * D_];
__device__ float g_qc [(size_t)BH_ * T_ * D_];
__device__ float g_cv1[(size_t)BH_ * T_ * D_];
__device__ float g_cv2[(size_t)BH_ * T_ * D_];
__device__ float g_diff[(size_t)B_ * T_ * C_];
__device__ uint32_t g_mbits[(size_t)T_ * (T_/32)];
// pre-converted K, V (single fp16), layout [z][n][64]
__device__ __half g_kxf[(size_t)BH_ * T_ * D_];
__device__ __half g_vxf[(size_t)BH_ * T_ * D_];
__device__ __half g_kyf[(size_t)BH_ * M_ * D_];
__device__ __half g_vyf[(size_t)BH_ * M_ * D_];

// ---------------------------------------------------------------------------
// Small PTX helpers
// ---------------------------------------------------------------------------
__device__ __forceinline__ uint32_t smem_u32(const void* p) {
    uint32_t a;
    asm("{ .reg .u64 t; cvta.to.shared.u64 t, %1; cvt.u32.u64 %0, t; }" : "=r"(a) : "l"(p));
    return a;
}
__device__ __forceinline__ void ldsm4(uint32_t* r, uint32_t a) {
    asm volatile("ldmatrix.sync.aligned.m8n8.x4.shared.b16 {%0,%1,%2,%3}, [%4];"
                 : "=r"(r[0]), "=r"(r[1]), "=r"(r[2]), "=r"(r[3]) : "r"(a));
}
__device__ __forceinline__ void ldsm4t(uint32_t* r, uint32_t a) {
    asm volatile("ldmatrix.sync.aligned.m8n8.x4.trans.shared.b16 {%0,%1,%2,%3}, [%4];"
                 : "=r"(r[0]), "=r"(r[1]), "=r"(r[2]), "=r"(r[3]) : "r"(a));
}
__device__ __forceinline__ void ldsm2(uint32_t* r, uint32_t a) {
    asm volatile("ldmatrix.sync.aligned.m8n8.x2.shared.b16 {%0,%1}, [%2];"
                 : "=r"(r[0]), "=r"(r[1]) : "r"(a));
}
__device__ __forceinline__ void ldsm2t(uint32_t* r, uint32_t a) {
    asm volatile("ldmatrix.sync.aligned.m8n8.x2.trans.shared.b16 {%0,%1}, [%2];"
                 : "=r"(r[0]), "=r"(r[1]) : "r"(a));
}
__device__ __forceinline__ void mma_f16(float* c, const uint32_t* a, const uint32_t* b) {
    asm volatile(
        "mma.sync.aligned.m16n8k16.row.col.f32.f16.f16.f32 "
        "{%0,%1,%2,%3}, {%4,%5,%6,%7}, {%8,%9}, {%0,%1,%2,%3};"
        : "+f"(c[0]), "+f"(c[1]), "+f"(c[2]), "+f"(c[3])
        : "r"(a[0]), "r"(a[1]), "r"(a[2]), "r"(a[3]), "r"(b[0]), "r"(b[1]));
}
__device__ __forceinline__ void cp16(uint32_t dst, const void* src) {
    asm volatile("cp.async.cg.shared.global [%0], [%1], 16;" :: "r"(dst), "l"(src) : "memory");
}
#define CP_COMMIT() asm volatile("cp.async.commit_group;" ::: "memory")
template<int N>
__device__ __forceinline__ void cp_wait() {
    asm volatile("cp.async.wait_group %0;" :: "n"(N) : "memory");
}
// single fp16 pack
__device__ __forceinline__ uint32_t packh(float a, float b) {
    __half2 h = __floats2half2_rn(a, b);
    return *reinterpret_cast<uint32_t*>(&h);
}
// magic-number fast exp scaled by 2^-4: returns e^x / 16
__device__ __forceinline__ float fexpm(float x) {
    const float L2E = 1.4426950408889634f;
    const float MAG = 12582912.0f;   // 2^23 + 2^22
    float ym = fmaf(x, L2E, MAG);
    float nf = ym - MAG;
    float f  = fmaf(x, L2E, -nf);
    float p = 1.3333558e-3f;
    p = fmaf(p, f, 9.6181291e-3f);
    p = fmaf(p, f, 5.5504109e-2f);
    p = fmaf(p, f, 2.4022651e-1f);
    p = fmaf(p, f, 6.9314718e-1f);
    p = fmaf(p, f, 1.0f);
    uint32_t sb = (__float_as_uint(ym) << 23) + 0x3B800000u;  // 2^(n-4)
    return p * __uint_as_float(sb);
}

// ---------------------------------------------------------------------------
// mask -> bitwords
// ---------------------------------------------------------------------------
__global__ __launch_bounds__(256)
void mask2bits(const int* __restrict__ mask, uint32_t* __restrict__ bits)
{
    int wid  = (blockIdx.x * 256 + threadIdx.x) >> 5;
    int lane = threadIdx.x & 31;
    int row  = wid >> 6;
    int col  = ((wid & 63) << 5) + lane;
    uint32_t b = __ballot_sync(0xffffffffu, mask[(size_t)row * T_ + col] != 0);
    if (lane == 0) bits[wid] = b;
}

// ---------------------------------------------------------------------------
// presplit: K, V -> single fp16 [z][n][64]
// ---------------------------------------------------------------------------
template<int NR>
__global__ __launch_bounds__(256)
void presplit(const float* __restrict__ qkv,
              __half* __restrict__ Kf, __half* __restrict__ Vf)
{
    size_t i = (size_t)blockIdx.x * 256 + threadIdx.x;
    int c4 = (int)(i & 127) << 2;
    int n  = (int)((i >> 7) % NR);
    int b  = (int)((i >> 7) / NR);
    int h  = c4 >> 6, d = c4 & 63;
    const float* row = qkv + ((size_t)b * NR + n) * (3 * C_);
    float4 kv = *reinterpret_cast<const float4*>(row + C_ + c4);
    float4 vv = *reinterpret_cast<const float4*>(row + 2 * C_ + c4);
    size_t o = ((size_t)(b * H_ + h) * NR + n) * D_ + d;
    uint2 kp = make_uint2(packh(kv.x, kv.y), packh(kv.z, kv.w));
    *reinterpret_cast<uint2*>(Kf + o) = kp;
    uint2 vp = make_uint2(packh(vv.x, vv.y), packh(vv.z, vv.w));
    *reinterpret_cast<uint2*>(Vf + o) = vp;
}

// ---------------------------------------------------------------------------
// Tensor-core GEMM, pure fp16 single-pass (A single fp16, B single fp16).
// Error ~2^-11 input quantization on A and B; all operands range-safe.
// ---------------------------------------------------------------------------
template<int BN, bool TRANSB, bool BIAS>
__global__ __launch_bounds__(256)
void mma_gemm(const float* __restrict__ A, const float* __restrict__ Bm,
              const float* __restrict__ bias, float* __restrict__ C,
              int K, int lda, int ldb, int ldc,
              long sAo, long sAi, long sBo, long sBi, long sCo, long sCi,
              int innerH, float alpha)
{
    constexpr int BM = 128;
    constexpr int WGN = BN / 32;
    constexpr int WGM = 8 / WGN;
    constexpr int WM  = BM / WGM;
    constexpr int MT  = WM / 16;
    constexpr int NT  = 4;
    constexpr int AP  = 24;
    constexpr int BP  = TRANSB ? 24 : (BN + 8);
    constexpr int BROWS = TRANSB ? BN : 16;
    constexpr int NBLD = TRANSB ? 2 : 1;

    __shared__ __align__(16) __half Ah[2][BM * AP];
    __shared__ __align__(16) __half Bh[2][BROWS * BP];

    const int tid  = threadIdx.x;
    const int lane = tid & 31;
    const int w    = tid >> 5;
    const int wm   = (w / WGN) * WM;
    const int wn   = (w % WGN) * 32;

    const int z  = blockIdx.z;
    const int zo = z / innerH;
    const int zi = z - zo * innerH;
    A  += (size_t)zo * sAo + (size_t)zi * sAi;
    Bm += (size_t)zo * sBo + (size_t)zi * sBi;
    C  += (size_t)zo * sCo + (size_t)zi * sCi;

    const int m0 = blockIdx.y * BM;
    const int n0 = blockIdx.x * BN;

    float acc[MT][NT][4];
#pragma unroll
    for (int i = 0; i < MT; i++)
#pragma unroll
        for (int j = 0; j < NT; j++)
#pragma unroll
            for (int q = 0; q < 4; q++) acc[i][j][q] = 0.f;

    const uint32_t aOff = (uint32_t)(((wm + (lane & 15)) * AP + (lane >> 4) * 8) * 2);
    uint32_t bOff;
    if (TRANSB) bOff = (uint32_t)(((wn + (lane & 7)) * BP + ((lane >> 3) & 1) * 8) * 2);
    else        bOff = (uint32_t)(((lane & 15) * BP + wn) * 2);

    const uint32_t ahB[2] = { smem_u32(&Ah[0][0]), smem_u32(&Ah[1][0]) };
    const uint32_t bhB[2] = { smem_u32(&Bh[0][0]), smem_u32(&Bh[1][0]) };

    const int NKB = K >> 4;
    float4 ra[2], rb[2];

#pragma unroll
    for (int l = 0; l < 2; l++) {
        int idx = l * 256 + tid;
        int r = idx >> 2, c = (idx & 3) << 2;
        ra[l] = *reinterpret_cast<const float4*>(A + (size_t)(m0 + r) * lda + c);
    }
#pragma unroll
    for (int l = 0; l < NBLD; l++) {
        if (TRANSB) {
            int idx = l * 256 + tid;
            int r = idx >> 2, c = (idx & 3) << 2;
            rb[l] = *reinterpret_cast<const float4*>(Bm + (size_t)(n0 + r) * ldb + c);
        } else {
            int r = tid >> 4, c = (tid & 15) << 2;
            rb[l] = *reinterpret_cast<const float4*>(Bm + (size_t)r * ldb + n0 + c);
        }
    }
    {
#pragma unroll
        for (int l = 0; l < 2; l++) {
            int idx = l * 256 + tid;
            int r = idx >> 2, c = (idx & 3) << 2;
            uint2 ap = make_uint2(packh(ra[l].x, ra[l].y), packh(ra[l].z, ra[l].w));
            *reinterpret_cast<uint2*>(&Ah[0][r * AP + c]) = ap;
        }
#pragma unroll
        for (int l = 0; l < NBLD; l++) {
            int r, c;
            if (TRANSB) { int idx = l * 256 + tid; r = idx >> 2; c = (idx & 3) << 2; }
            else        { r = tid >> 4; c = (tid & 15) << 2; }
            uint2 bp = make_uint2(packh(rb[l].x, rb[l].y), packh(rb[l].z, rb[l].w));
            *reinterpret_cast<uint2*>(&Bh[0][r * BP + c]) = bp;
        }
    }
    __syncthreads();

    for (int kb = 0; kb < NKB; kb++) {
        const int s = kb & 1;
        if (kb + 1 < NKB) {
            const int kof = (kb + 1) << 4;
#pragma unroll
            for (int l = 0; l < 2; l++) {
                int idx = l * 256 + tid;
                int r = idx >> 2, c = (idx & 3) << 2;
                ra[l] = *reinterpret_cast<const float4*>(A + (size_t)(m0 + r) * lda + kof + c);
            }
#pragma unroll
            for (int l = 0; l < NBLD; l++) {
                if (TRANSB) {
                    int idx = l * 256 + tid;
                    int r = idx >> 2, c = (idx & 3) << 2;
                    rb[l] = *reinterpret_cast<const float4*>(Bm + (size_t)(n0 + r) * ldb + kof + c);
                } else {
                    int r = tid >> 4, c = (tid & 15) << 2;
                    rb[l] = *reinterpret_cast<const float4*>(Bm + (size_t)(kof + r) * ldb + n0 + c);
                }
            }
        }

        uint32_t ah[MT][4], bh[NT][2];
#pragma unroll
        for (int mt = 0; mt < MT; mt++) {
            uint32_t o = aOff + (uint32_t)(mt * 16 * AP * 2);
            ldsm4(ah[mt], ahB[s] + o);
        }
#pragma unroll
        for (int nt = 0; nt < NT; nt++) {
            if (TRANSB) {
                uint32_t o = bOff + (uint32_t)(nt * 8 * BP * 2);
                ldsm2(bh[nt], bhB[s] + o);
            } else {
                uint32_t o = bOff + (uint32_t)(nt * 8 * 2);
                ldsm2t(bh[nt], bhB[s] + o);
            }
        }
#pragma unroll
        for (int mt = 0; mt < MT; mt++)
#pragma unroll
            for (int nt = 0; nt < NT; nt++)
                mma_f16(acc[mt][nt], ah[mt], bh[nt]);

        if (kb + 1 < NKB) {
            const int sn = (kb + 1) & 1;
#pragma unroll
            for (int l = 0; l < 2; l++) {
                int idx = l * 256 + tid;
                int r = idx >> 2, c = (idx & 3) << 2;
                uint2 ap = make_uint2(packh(ra[l].x, ra[l].y), packh(ra[l].z, ra[l].w));
                *reinterpret_cast<uint2*>(&Ah[sn][r * AP + c]) = ap;
            }
#pragma unroll
            for (int l = 0; l < NBLD; l++) {
                int r, c;
                if (TRANSB) { int idx = l * 256 + tid; r = idx >> 2; c = (idx & 3) << 2; }
                else        { r = tid >> 4; c = (tid & 15) << 2; }
                uint2 bp = make_uint2(packh(rb[l].x, rb[l].y), packh(rb[l].z, rb[l].w));
                *reinterpret_cast<uint2*>(&Bh[sn][r * BP + c]) = bp;
            }
        }
        __syncthreads();
    }

    const int g = lane >> 2, q = lane & 3;
#pragma unroll
    for (int mt = 0; mt < MT; mt++) {
#pragma unroll
        for (int nt = 0; nt < NT; nt++) {
            int r0 = m0 + wm + mt * 16 + g;
            int cc = n0 + wn + nt * 8 + q * 2;
            float2 v0, v1;
            v0.x = alpha * acc[mt][nt][0];
            v0.y = alpha * acc[mt][nt][1];
            v1.x = alpha * acc[mt][nt][2];
            v1.y = alpha * acc[mt][nt][3];
            if (BIAS) {
                float b0 = bias[cc], b1 = bias[cc + 1];
                v0.x += b0; v0.y += b1; v1.x += b0; v1.y += b1;
            }
            *reinterpret_cast<float2*>(C + (size_t)r0 * ldc + cc) = v0;
            *reinterpret_cast<float2*>(C + (size_t)(r0 + 8) * ldc + cc) = v1;
        }
    }
}

// ---------------------------------------------------------------------------
// Merged flash attention (minimal-HMMA): 1 pass scores + 1 pass AV, fp16.
// Stage (18432B): K fp16 +0, V fp16 +9216; rows 64, pitch 144B.
// ---------------------------------------------------------------------------
#define FB_STAGE 18432

__global__ __launch_bounds__(128, 4)
void flash_both(const float* __restrict__ qc, const float* __restrict__ qkvx,
                const uint32_t* __restrict__ mbits,
                const __half* __restrict__ kxf, const __half* __restrict__ vxf,
                const __half* __restrict__ kyf, const __half* __restrict__ vyf,
                float* __restrict__ cv2, float* __restrict__ cv1, float scale)
{
    extern __shared__ __align__(16) char smbuf[];
    const uint32_t sbase = smem_u32(smbuf);

    const int tid = threadIdx.x, lane = tid & 31, w = tid >> 5;
    const int g = lane >> 2, q = lane & 3;
    const int wm = w * 16;

    const int zz = blockIdx.y;
    const bool pA = (zz < BH_);
    const int z  = pA ? zz : zz - BH_;
    const int zo = z / H_, zi = z - zo * H_;

    const float* Q;  int ldq;
    const __half *KF, *VF;
    float alpha; int ntiles;
    const uint32_t* mb;
    float* O;
    if (pA) {
        Q = qc + (size_t)z * T_ * D_;  ldq = D_;
        size_t zo_ = (size_t)z * T_ * D_;
        KF = kxf + zo_; VF = vxf + zo_;
        alpha = 1.0f; ntiles = T_ / 64; mb = mbits; O = cv2;
    } else {
        Q = qkvx + ((size_t)zo * T_) * (3*C_) + zi * D_;  ldq = 3*C_;
        size_t zo_ = (size_t)z * M_ * D_;
        KF = kyf + zo_; VF = vyf + zo_;
        alpha = scale; ntiles = M_ / 64; mb = nullptr; O = cv1;
    }
    const int m0 = blockIdx.x * 64;

    // ---- load Q tile (alpha folded), single fp16 in smem, pull frags ----
    {
        __half* Qh = (__half*)smbuf;
#pragma unroll
        for (int l = 0; l < 8; l++) {
            int idx = l * 128 + tid;
            int r = idx >> 4, cc = (idx & 15) << 2;
            float4 v = *reinterpret_cast<const float4*>(Q + (size_t)(m0 + r) * ldq + cc);
            v.x *= alpha; v.y *= alpha; v.z *= alpha; v.w *= alpha;
            uint2 hp = make_uint2(packh(v.x, v.y), packh(v.z, v.w));
            *reinterpret_cast<uint2*>(&Qh[r * 72 + cc]) = hp;
        }
    }
    __syncthreads();
    uint32_t qh[4][4];
    {
        const uint32_t ao = sbase + (uint32_t)(((wm + (lane & 15)) * 72 + (lane >> 4) * 8) * 2);
#pragma unroll
        for (int kc = 0; kc < 4; kc++)
            ldsm4(qh[kc], ao + kc * 32);
    }
    __syncthreads();

    float oacc[8][4];
#pragma unroll
    for (int nt = 0; nt < 8; nt++)
#pragma unroll
        for (int e = 0; e < 4; e++) oacc[nt][e] = 0.f;
    float ps0 = 0.f, ps1 = 0.f;

    const uint32_t kfo = (uint32_t)((((lane & 7) + ((lane >> 4) << 3)) * 72
                                     + ((lane >> 3) & 1) * 8) * 2);
    const uint32_t vfo = (uint32_t)(((lane & 15) * 72 + (lane >> 4) * 8) * 2);
    const int row0 = m0 + wm + g;
    const uint32_t* mrow0p = mb ? (mb + (size_t)row0 * (T_/32)) : nullptr;

    const char* kvbase[2] = { (const char*)KF, (const char*)VF };

    auto load_tile = [&](int s, int n0) {
        const uint32_t sb = sbase + s * FB_STAGE;
#pragma unroll
        for (int l = 0; l < 8; l++) {
            const int arr = l >> 2;
            const int rem = ((l & 3) << 7) + tid;
            const int r = rem >> 3, c = rem & 7;
            cp16(sb + arr * 9216 + r * 144 + c * 16,
                 kvbase[arr] + (size_t)(n0 + r) * 128 + c * 16);
        }
        CP_COMMIT();
    };

    load_tile(0, 0);

    for (int j = 0; j < ntiles; j++) {
        const int n0 = j * 64;
        const int s = j & 1;

        cp_wait<0>();
        __syncthreads();
        if (j + 1 < ntiles) load_tile(1 - s, n0 + 64);

        const uint32_t khb = sbase + s * FB_STAGE;
        const uint32_t vhb = khb + 9216;

        uint2 a0 = make_uint2(0xffffffffu, 0xffffffffu);
        uint2 a1 = make_uint2(0xffffffffu, 0xffffffffu);
        if (mrow0p) {
            const uint32_t* mp = mrow0p + (n0 >> 5);
            a0 = *reinterpret_cast<const uint2*>(mp);
            a1 = *reinterpret_cast<const uint2*>(mp + 8 * (T_/32));
        }

        // ---- scores S = Q @ K^T : single fp16 pass ----
        float s_[8][4];
#pragma unroll
        for (int nt = 0; nt < 8; nt++)
#pragma unroll
            for (int e = 0; e < 4; e++) s_[nt][e] = 0.f;
#pragma unroll
        for (int kc = 0; kc < 4; kc++) {
            uint32_t kf[4][4];
#pragma unroll
            for (int ntp = 0; ntp < 4; ntp++)
                ldsm4(kf[ntp], khb + kfo + (uint32_t)(ntp * (16 * 72 * 2)) + kc * 32);
#pragma unroll
            for (int ntp = 0; ntp < 4; ntp++) {
                mma_f16(s_[2*ntp],   qh[kc], &kf[ntp][0]);
                mma_f16(s_[2*ntp+1], qh[kc], &kf[ntp][2]);
            }
        }

        // ---- exp (scaled 2^-4), mask-zero, partial sums ----
#pragma unroll
        for (int nt = 0; nt < 8; nt++) {
            s_[nt][0] = fexpm(s_[nt][0]);
            s_[nt][1] = fexpm(s_[nt][1]);
            s_[nt][2] = fexpm(s_[nt][2]);
            s_[nt][3] = fexpm(s_[nt][3]);
        }
        if (mrow0p) {
#pragma unroll
            for (int nt = 0; nt < 8; nt++) {
                uint32_t w0 = (nt < 4) ? a0.x : a0.y;
                uint32_t w1 = (nt < 4) ? a1.x : a1.y;
                int b = ((nt * 8) & 31) + q * 2;
                if (!((w0 >> b) & 1u))       s_[nt][0] = 0.f;
                if (!((w0 >> (b+1)) & 1u))   s_[nt][1] = 0.f;
                if (!((w1 >> b) & 1u))       s_[nt][2] = 0.f;
                if (!((w1 >> (b+1)) & 1u))   s_[nt][3] = 0.f;
            }
        }
#pragma unroll
        for (int nt = 0; nt < 8; nt++) {
            ps0 += s_[nt][0] + s_[nt][1];
            ps1 += s_[nt][2] + s_[nt][3];
        }

        // ---- O += P @ V : single fp16 pass ----
#pragma unroll
        for (int kc = 0; kc < 4; kc++) {
            uint32_t ph[4];
            ph[0] = packh(s_[2*kc][0],   s_[2*kc][1]);
            ph[1] = packh(s_[2*kc][2],   s_[2*kc][3]);
            ph[2] = packh(s_[2*kc+1][0], s_[2*kc+1][1]);
            ph[3] = packh(s_[2*kc+1][2], s_[2*kc+1][3]);
            uint32_t vf[4][4];
#pragma unroll
            for (int ntp = 0; ntp < 4; ntp++)
                ldsm4t(vf[ntp], vhb + vfo + (uint32_t)((kc * 16 * 72 + ntp * 16) * 2));
#pragma unroll
            for (int ntp = 0; ntp < 4; ntp++) {
                mma_f16(oacc[2*ntp],   ph, &vf[ntp][0]);
                mma_f16(oacc[2*ntp+1], ph, &vf[ntp][2]);
            }
        }
    }

    // ---- final row-sum reduction + write ----
    ps0 += __shfl_xor_sync(0xffffffffu, ps0, 1);
    ps0 += __shfl_xor_sync(0xffffffffu, ps0, 2);
    ps1 += __shfl_xor_sync(0xffffffffu, ps1, 1);
    ps1 += __shfl_xor_sync(0xffffffffu, ps1, 2);
    const float inv0 = 1.f / ps0;
    const float inv1 = 1.f / ps1;
    float* Ob = O + (size_t)z * T_ * D_;
#pragma unroll
    for (int nt = 0; nt < 8; nt++) {
        int cc = nt * 8 + q * 2;
        float2 v0, v1;
        v0.x = oacc[nt][0] * inv0; v0.y = oacc[nt][1] * inv0;
        v1.x = oacc[nt][2] * inv1; v1.y = oacc[nt][3] * inv1;
        *reinterpret_cast<float2*>(Ob + (size_t)row0 * D_ + cc) = v0;
        *reinterpret_cast<float2*>(Ob + (size_t)(row0 + 8) * D_ + cc) = v1;
    }
}

// ---------------------------------------------------------------------------
// gmat partials + reduce (fp32 exact — G feeds everything downstream)
// ---------------------------------------------------------------------------
__global__ __launch_bounds__(256)
void gmat_partial(const float* __restrict__ qkvy, float* __restrict__ Gp)
{
    const int z = blockIdx.x;
    const int sl = blockIdx.y;
    const int b = z / H_, h = z % H_;
    const float* base = qkvy + ((size_t)b * M_ + sl * 64) * (3 * C_);
    const int kcol = C_ + h * D_;
    const int qcol = h * D_;

    __shared__ float Ks[32][D_];
    __shared__ float Qs[32][D_];

    const int tid = threadIdx.x;
    const int ti = tid / 16, tj = tid % 16;

    float acc[4][4];
#pragma unroll
    for (int i = 0; i < 4; i++)
#pragma unroll
        for (int j = 0; j < 4; j++) acc[i][j] = 0.f;

    for (int m0 = 0; m0 < 64; m0 += 32) {
#pragma unroll
        for (int i = 0; i < 2; i++) {
            int qq = (i * 256 + tid) * 4;
            int r = qq / D_, c = qq % D_;
            const float* rowp = base + (size_t)(m0 + r) * (3 * C_);
            *reinterpret_cast<float4*>(&Ks[r][c]) =
                *reinterpret_cast<const float4*>(rowp + kcol + c);
            *reinterpret_cast<float4*>(&Qs[r][c]) =
                *reinterpret_cast<const float4*>(rowp + qcol + c);
        }
        __syncthreads();
#pragma unroll
        for (int mm = 0; mm < 32; mm++) {
            float kv[4], qv[4];
#pragma unroll
            for (int i = 0; i < 4; i++) kv[i] = Ks[mm][ti * 4 + i];
#pragma unroll
            for (int j = 0; j < 4; j++) qv[j] = Qs[mm][tj * 4 + j];
#pragma unroll
            for (int i = 0; i < 4; i++)
#pragma unroll
                for (int j = 0; j < 4; j++)
                    acc[i][j] = fmaf(kv[i], qv[j], acc[i][j]);
        }
        __syncthreads();
    }

    float* Gz = Gp + ((size_t)(z * 16 + sl) << 12);
#pragma unroll
    for (int i = 0; i < 4; i++)
#pragma unroll
        for (int j = 0; j < 4; j++)
            Gz[(ti * 4 + i) * D_ + tj * 4 + j] = acc[i][j];
}

__global__ __launch_bounds__(256)
void gmat_reduce(const float* __restrict__ Gp, float* __restrict__ G, float alpha)
{
    int i = blockIdx.x * 256 + threadIdx.x;
    int z = i >> 12;
    int e = i & 4095;
    float s = 0.f;
#pragma unroll
    for (int sl = 0; sl < 16; sl++)
        s += Gp[((size_t)(z * 16 + sl) << 12) + e];
    G[i] = alpha * s;
}

// ---------------------------------------------------------------------------
// diff + head-merge transpose
// ---------------------------------------------------------------------------
__global__ __launch_bounds__(256)
void diff_kernel(const float* __restrict__ a, const float* __restrict__ b,
                 float* __restrict__ o)
{
    int i = blockIdx.x * blockDim.x + threadIdx.x;
    int d  = i & (D_ - 1);
    int t  = (i >> 6) & (T_ - 1);
    int h  = (i >> 17) & (H_ - 1);
    int bb = i >> 20;
    o[((size_t)(bb * T_ + t)) * C_ + h * D_ + d] = a[i] - b[i];
}

// ---------------------------------------------------------------------------
// Launcher
// ---------------------------------------------------------------------------
extern "C" void kernel_launch(void* const* d_in, const int* in_sizes, int n_in,
                              void* d_out, int out_size)
{
    const float* x      = (const float*)d_in[0];
    const float* y      = (const float*)d_in[1];
    const int*   mask   = (const int*)  d_in[2];
    const float* qkv_w  = (const float*)d_in[3];
    const float* qkv_b  = (const float*)d_in[4];
    const float* proj_w = (const float*)d_in[5];
    const float* proj_b = (const float*)d_in[6];
    float* out = (float*)d_out;

    float *qkvx, *qkvy, *Gp, *G, *qc, *cv1, *cv2, *dif;
    uint32_t* mbits;
    __half *kxf, *vxf, *kyf, *vyf;
    cudaGetSymbolAddress((void**)&qkvx, g_qkvx);
    cudaGetSymbolAddress((void**)&qkvy, g_qkvy);
    cudaGetSymbolAddress((void**)&Gp,   g_Gp);
    cudaGetSymbolAddress((void**)&G,    g_G);
    cudaGetSymbolAddress((void**)&qc,   g_qc);
    cudaGetSymbolAddress((void**)&cv1,  g_cv1);
    cudaGetSymbolAddress((void**)&cv2,  g_cv2);
    cudaGetSymbolAddress((void**)&dif,  g_diff);
    cudaGetSymbolAddress((void**)&mbits, g_mbits);
    cudaGetSymbolAddress((void**)&kxf, g_kxf);
    cudaGetSymbolAddress((void**)&vxf, g_vxf);
    cudaGetSymbolAddress((void**)&kyf, g_kyf);
    cudaGetSymbolAddress((void**)&vyf, g_vyf);

    cudaFuncSetAttribute(flash_both,
                         cudaFuncAttributeMaxDynamicSharedMemorySize, 2 * FB_STAGE);

    const float scale  = 0.125f;
    const float scale3 = scale * scale * scale;
    const long ZL = 0;

    // 0) mask -> bitwords
    mask2bits<<<(T_ * (T_/32)) / 8, 256>>>(mask, mbits);

    // 1) qkv_x = x @ qkv_w^T + qkv_b
    mma_gemm<128,true,true><<<dim3(1536/128, (B_*T_)/128, 1), 256>>>(
        x, qkv_w, qkv_b, qkvx, C_, C_, C_, 3*C_,
        ZL, ZL, ZL, ZL, ZL, ZL, 1, 1.0f);

    // 2) qkv_y = y @ qkv_w^T + qkv_b
    mma_gemm<128,true,true><<<dim3(1536/128, (B_*M_)/128, 1), 256>>>(
        y, qkv_w, qkv_b, qkvy, C_, C_, C_, 3*C_,
        ZL, ZL, ZL, ZL, ZL, ZL, 1, 1.0f);

    // 2b) pre-convert K, V to fp16
    presplit<T_><<<(B_*T_*128)/256, 256>>>(qkvx, kxf, vxf);
    presplit<M_><<<(B_*M_*128)/256, 256>>>(qkvy, kyf, vyf);

    // 3) G = scale^3 * Ky^T Qy
    gmat_partial<<<dim3(BH_, 16), 256>>>(qkvy, Gp);
    gmat_reduce<<<(BH_ * D_ * D_) / 256, 256>>>(Gp, G, scale3);

    // 4) Qc[z] = Qx @ G[z]
    mma_gemm<64,false,false><<<dim3(1, T_/128, BH_), 256>>>(
        qkvx, G, nullptr, qc,
        D_, 3*C_, D_, D_,
        (long)T_*3*C_, (long)D_,
        (long)H_*D_*D_, (long)D_*D_,
        (long)H_*T_*D_, (long)T_*D_,
        H_, 1.0f);

    // 5+6) both flash branches in ONE launch
    flash_both<<<dim3(T_/64, 2*BH_), 128, 2*FB_STAGE>>>(
        qc, qkvx, mbits,
        kxf, vxf, kyf, vyf,
        cv2, cv1, scale);

    // 7) diff + merge heads
    diff_kernel<<<(B_*H_*T_*D_)/256, 256>>>(cv1, cv2, dif);

    // 8) out = diff @ proj_w^T + proj_b
    mma_gemm<128,true,true><<<dim3(C_/128, (B_*T_)/128, 1), 256>>>(
        dif, proj_w, proj_b, out, C_, C_, C_, C_,
        ZL, ZL, ZL, ZL, ZL, ZL, 1, 1.0f);
}